// round 6
// baseline (speedup 1.0000x reference)
#include <cuda_runtime.h>
#include <cstdint>

// ---------------------------------------------------------------------------
// Problem constants
// ---------------------------------------------------------------------------
#define B_ROWS  16384
#define D_DIM   784
#define C_DIM   2048
#define OUT_DIM 10

#define KPAD   800               // 784 padded to 25*32 (int8 bytes)
#define KWORDS 200               // KPAD/4
#define KB     160               // K bytes per pipeline block
#define NKBLK  5                 // blocks per chunk (5*160 = 800)
#define NK32   5                 // k32 steps per block (160/32)
#define TM     128               // x rows per CTA
#define TN     128               // centres per chunk
#define NSLICE 8                 // C split across CTAs
#define CHPS   2                 // chunks per slice (256 centres)
#define NGBLK  (CHPS * NKBLK)    // 10 blocks per CTA
#define NTHREADS 256

// smem tile stride: 160 data + 16 pad bytes
#define ASTB  176
#define TILEB 22528u             // 128 * 176
#define WST   12                 // floats per Wcol row (10 + 2 pad)

// smem byte offsets
#define OFF_A    0u              // 2 x 22528 = 45056
#define OFF_B    45056u          // 2 x 22528 = 45056
#define OFF_WCOL 90112u          // 128 x 12 x 4 = 6144
#define OFF_C2   96256u          // 128 x 4
#define OFF_IS2  96768u
#define OFF_SC   97280u
#define SMEM_TOTAL 97792u
#define OFF_RED  OFF_A           // final reduction overlays A buffer

// ---------------------------------------------------------------------------
// Device-global scratch (no allocations allowed)
// ---------------------------------------------------------------------------
__device__ __align__(16) uint32_t g_xq[(size_t)B_ROWS * KWORDS];   // 13.1 MB int8
__device__ __align__(16) uint32_t g_cq[(size_t)C_DIM * KWORDS];    // 1.6 MB int8
__device__ float g_x2[B_ROWS];
__device__ float g_sx[B_ROWS];
__device__ float g_c2[C_DIM];
__device__ float g_sc[C_DIM];
__device__ float g_is2[C_DIM];
__device__ float g_part[(size_t)NSLICE * B_ROWS * OUT_DIM];        // 5.2 MB

// ---------------------------------------------------------------------------
// PTX helpers (base-ISA sm_75/80 era; valid for compute_103 virtual arch)
// ---------------------------------------------------------------------------
__device__ __forceinline__ uint32_t smem_u32(const void* p) {
    uint32_t a;
    asm("{ .reg .u64 t; cvta.to.shared.u64 t, %1; cvt.u32.u64 %0, t; }" : "=r"(a) : "l"(p));
    return a;
}

__device__ __forceinline__ void cp16(uint32_t dst, const void* src) {
    asm volatile("cp.async.cg.shared.global [%0], [%1], 16;" :: "r"(dst), "l"(src));
}
#define CP_COMMIT() asm volatile("cp.async.commit_group;" ::: "memory")
#define CP_WAIT0()  asm volatile("cp.async.wait_group 0;"  ::: "memory")

__device__ __forceinline__ void ldm_x4(uint32_t* r, uint32_t addr) {
    asm volatile("ldmatrix.sync.aligned.m8n8.x4.shared.b16 {%0,%1,%2,%3}, [%4];"
                 : "=r"(r[0]), "=r"(r[1]), "=r"(r[2]), "=r"(r[3]) : "r"(addr));
}

// int8 MMA: m16n8k32, s32 accum (sm_75+ base ISA)
__device__ __forceinline__ void mma16832_s8(int* c, const uint32_t* a, const uint32_t* b) {
    asm volatile(
        "mma.sync.aligned.m16n8k32.row.col.s32.s8.s8.s32 "
        "{%0,%1,%2,%3}, {%4,%5,%6,%7}, {%8,%9}, {%0,%1,%2,%3};"
        : "+r"(c[0]), "+r"(c[1]), "+r"(c[2]), "+r"(c[3])
        : "r"(a[0]), "r"(a[1]), "r"(a[2]), "r"(a[3]), "r"(b[0]), "r"(b[1]));
}

__device__ __forceinline__ int q8(float v, float inv) {
    int q = __float2int_rn(v * inv);
    return max(-127, min(127, q));
}

// ---------------------------------------------------------------------------
// Fused prep: per-row symmetric int8 quantization + squared norms.
// One warp per row; handles both x (rows < B_ROWS) and centres.
// ---------------------------------------------------------------------------
__global__ void prep_kernel(const float* __restrict__ x,
                            const float* __restrict__ c,
                            const float* __restrict__ ls) {
    const int gw   = (blockIdx.x * blockDim.x + threadIdx.x) >> 5;
    const int lane = threadIdx.x & 31;
    const bool isX = gw < B_ROWS;
    const int row  = isX ? gw : gw - B_ROWS;
    if (!isX && row >= C_DIM) return;

    const float4* src = (const float4*)((isX ? x : c) + (size_t)row * D_DIM);
    uint32_t* dst = (isX ? g_xq : g_cq) + (size_t)row * KWORDS;

    float4 v[7];
    float s = 0.f, mx = 0.f;
    #pragma unroll
    for (int i = 0; i < 7; i++) {
        const int w = lane + i * 32;
        v[i] = (w < D_DIM / 4) ? src[w] : make_float4(0.f, 0.f, 0.f, 0.f);
        s = fmaf(v[i].x, v[i].x, fmaf(v[i].y, v[i].y,
            fmaf(v[i].z, v[i].z, fmaf(v[i].w, v[i].w, s))));
        mx = fmaxf(mx, fmaxf(fmaxf(fabsf(v[i].x), fabsf(v[i].y)),
                             fmaxf(fabsf(v[i].z), fabsf(v[i].w))));
    }
    #pragma unroll
    for (int m = 16; m; m >>= 1) {
        s  += __shfl_xor_sync(0xffffffffu, s, m);
        mx  = fmaxf(mx, __shfl_xor_sync(0xffffffffu, mx, m));
    }
    const float inv = (mx > 0.f) ? (127.f / mx) : 0.f;
    const float scl = mx * (1.f / 127.f);

    #pragma unroll
    for (int i = 0; i < 7; i++) {
        const int w = lane + i * 32;
        if (w < KWORDS) {
            uint32_t u = ((uint32_t)(q8(v[i].x, inv) & 255))
                       | ((uint32_t)(q8(v[i].y, inv) & 255) << 8)
                       | ((uint32_t)(q8(v[i].z, inv) & 255) << 16)
                       | ((uint32_t)(q8(v[i].w, inv) & 255) << 24);
            dst[w] = u;
        }
    }
    if (lane == 0) {
        if (isX) { g_x2[row] = s; g_sx[row] = scl; }
        else     { g_c2[row] = s; g_sc[row] = scl; g_is2[row] = __expf(-2.f * ls[row]); }
    }
}

// ---------------------------------------------------------------------------
// Main kernel: int8 mma, 8-way C-slice, register epilogue with underflow skip
// ---------------------------------------------------------------------------
__global__ __launch_bounds__(NTHREADS, 1)
void rbf_mma_kernel(const float* __restrict__ W) {
    extern __shared__ char sm[];
    const uint32_t sbase = smem_u32(sm);

    const int tid  = threadIdx.x;
    const int wid  = tid >> 5;
    const int lane = tid & 31;
    const int wm   = wid & 3;
    const int wn   = wid >> 2;
    const int lm   = lane >> 2;
    const int ln   = (lane & 3) * 2;

    const int m_tile = blockIdx.x >> 3;
    const int slice  = blockIdx.x & (NSLICE - 1);
    const int m0     = m_tile * TM;
    const int chunk0 = slice * CHPS;

    float* c2S   = (float*)(sm + OFF_C2);
    float* is2S  = (float*)(sm + OFF_IS2);
    float* scS   = (float*)(sm + OFF_SC);
    float* WcolS = (float*)(sm + OFF_WCOL);

    // per-thread fixed rows: a0, b0, a1, b1
    const int ra0 = m0 + wm * 32 + lm;
    const float x2a0 = g_x2[ra0],      s2a0 = 2.f * g_sx[ra0];
    const float x2b0 = g_x2[ra0 + 8],  s2b0 = 2.f * g_sx[ra0 + 8];
    const float x2a1 = g_x2[ra0 + 16], s2a1 = 2.f * g_sx[ra0 + 16];
    const float x2b1 = g_x2[ra0 + 24], s2b1 = 2.f * g_sx[ra0 + 24];

    float oacc[4][OUT_DIM];
    #pragma unroll
    for (int i = 0; i < 4; i++)
        #pragma unroll
        for (int o = 0; o < OUT_DIM; o++) oacc[i][o] = 0.f;

    // preload block g=0 (chunk0, koff 0) into buf 0
    {
        const int n0 = chunk0 * TN;
        #pragma unroll
        for (int i = 0; i < 5; i++) {
            int idx = tid + i * NTHREADS;       // 0..1279
            int r = idx / 10, ch = idx - r * 10;
            cp16(sbase + OFF_A + (uint32_t)r * ASTB + ch * 16,
                 (const char*)(g_xq + (size_t)(m0 + r) * KWORDS) + ch * 16);
            cp16(sbase + OFF_B + (uint32_t)r * ASTB + ch * 16,
                 (const char*)(g_cq + (size_t)(n0 + r) * KWORDS) + ch * 16);
        }
        CP_COMMIT();
    }

    for (int cl = 0; cl < CHPS; cl++) {
        const int chunk = chunk0 + cl;
        const int n0 = chunk * TN;

        if (tid < TN) {
            c2S[tid]  = g_c2[n0 + tid];
            is2S[tid] = g_is2[n0 + tid];
            scS[tid]  = g_sc[n0 + tid];
        }
        #pragma unroll
        for (int i = 0; i < 5; i++) {
            int idx = tid + i * NTHREADS;       // TN*OUT = 1280
            int cc = idx / OUT_DIM, o = idx - cc * OUT_DIM;
            WcolS[cc * WST + o] = W[(size_t)o * C_DIM + n0 + cc];
        }

        int acc[2][8][4];
        #pragma unroll
        for (int i = 0; i < 2; i++)
            #pragma unroll
            for (int j = 0; j < 8; j++)
                #pragma unroll
                for (int e = 0; e < 4; e++) acc[i][j][e] = 0;

        for (int kb = 0; kb < NKBLK; kb++) {
            const int g   = cl * NKBLK + kb;
            const int buf = g & 1;
            CP_WAIT0();
            __syncthreads();

            if (g + 1 < NGBLK) {
                const int gn   = g + 1;
                const int ncl  = gn / NKBLK;
                const int nkb  = gn - ncl * NKBLK;
                const int nn0  = (chunk0 + ncl) * TN;
                const int koff = nkb * KB;
                const uint32_t obuf = (uint32_t)(gn & 1) * TILEB;
                #pragma unroll
                for (int i = 0; i < 5; i++) {
                    int idx = tid + i * NTHREADS;
                    int r = idx / 10, ch = idx - r * 10;
                    cp16(sbase + OFF_A + obuf + (uint32_t)r * ASTB + ch * 16,
                         (const char*)(g_xq + (size_t)(m0 + r) * KWORDS) + koff + ch * 16);
                    cp16(sbase + OFF_B + obuf + (uint32_t)r * ASTB + ch * 16,
                         (const char*)(g_cq + (size_t)(nn0 + r) * KWORDS) + koff + ch * 16);
                }
                CP_COMMIT();
            }

            const uint32_t aBase = sbase + OFF_A + (uint32_t)buf * TILEB;
            const uint32_t bBase = sbase + OFF_B + (uint32_t)buf * TILEB;
            const uint32_t lrow  = (uint32_t)(lane & 15);
            const uint32_t lcol  = (uint32_t)(lane >> 4) * 16u;

            #pragma unroll
            for (int ks = 0; ks < NK32; ks++) {
                uint32_t af[2][4];
                #pragma unroll
                for (int mi = 0; mi < 2; mi++)
                    ldm_x4(af[mi], aBase + (uint32_t)(wm * 32 + mi * 16 + lrow) * ASTB
                                         + (uint32_t)ks * 32u + lcol);
                uint32_t bf[8][2];
                #pragma unroll
                for (int njj = 0; njj < 4; njj++) {
                    uint32_t r4[4];
                    ldm_x4(r4, bBase + (uint32_t)(wn * 64 + njj * 16 + lrow) * ASTB
                                     + (uint32_t)ks * 32u + lcol);
                    bf[njj * 2 + 0][0] = r4[0];
                    bf[njj * 2 + 1][0] = r4[1];
                    bf[njj * 2 + 0][1] = r4[2];
                    bf[njj * 2 + 1][1] = r4[3];
                }
                #pragma unroll
                for (int mi = 0; mi < 2; mi++)
                    #pragma unroll
                    for (int nf = 0; nf < 8; nf++)
                        mma16832_s8(acc[mi][nf], af[mi], bf[nf]);
            }
        }

        // ---- register epilogue: dequant, d2, exact underflow skip ----
        // dot = sx[r]*sc[c]*acc ; t = max(x2+c2-2*dot,0)*is2 ; exp(-t)==0 for t>104
        #pragma unroll
        for (int nf = 0; nf < 8; nf++) {
            const int c0 = wn * 64 + nf * 8 + ln;
            const int c1 = c0 + 1;
            const float cc0 = c2S[c0],  cc1 = c2S[c1];
            const float ii0 = is2S[c0], ii1 = is2S[c1];
            const float sc0 = scS[c0],  sc1 = scS[c1];
            #pragma unroll
            for (int mi = 0; mi < 2; mi++) {
                const float xa  = mi ? x2a1 : x2a0;
                const float xb  = mi ? x2b1 : x2b0;
                const float s2a = mi ? s2a1 : s2a0;
                const float s2b = mi ? s2b1 : s2b0;
                const float t00 = fmaxf(fmaf(-s2a * sc0, (float)acc[mi][nf][0], xa + cc0), 0.f) * ii0;
                const float t01 = fmaxf(fmaf(-s2a * sc1, (float)acc[mi][nf][1], xa + cc1), 0.f) * ii1;
                const float t10 = fmaxf(fmaf(-s2b * sc0, (float)acc[mi][nf][2], xb + cc0), 0.f) * ii0;
                const float t11 = fmaxf(fmaf(-s2b * sc1, (float)acc[mi][nf][3], xb + cc1), 0.f) * ii1;
                if (t00 < 104.f || t01 < 104.f || t10 < 104.f || t11 < 104.f) {
                    const float p00 = __expf(-t00);
                    const float p01 = __expf(-t01);
                    const float p10 = __expf(-t10);
                    const float p11 = __expf(-t11);
                    #pragma unroll
                    for (int o = 0; o < OUT_DIM; o++) {
                        const float w0 = WcolS[c0 * WST + o];
                        const float w1 = WcolS[c1 * WST + o];
                        oacc[mi * 2 + 0][o] = fmaf(p00, w0, fmaf(p01, w1, oacc[mi * 2 + 0][o]));
                        oacc[mi * 2 + 1][o] = fmaf(p10, w0, fmaf(p11, w1, oacc[mi * 2 + 1][o]));
                    }
                }
            }
        }
        __syncthreads();   // meta consumed before next chunk overwrites
    }

    // ---- in-CTA reduction, write partial buffer (no atomics) ----
    #pragma unroll
    for (int i = 0; i < 4; i++)
        #pragma unroll
        for (int o = 0; o < OUT_DIM; o++) {
            float v = oacc[i][o];
            v += __shfl_xor_sync(0xffffffffu, v, 1);
            v += __shfl_xor_sync(0xffffffffu, v, 2);
            oacc[i][o] = v;
        }

    float* redS = (float*)(sm + OFF_RED);
    if (wn == 0 && (lane & 3) == 0) {
        #pragma unroll
        for (int i = 0; i < 4; i++) {
            const int r = wm * 32 + (i >> 1) * 16 + (i & 1) * 8 + lm;
            #pragma unroll
            for (int o = 0; o < OUT_DIM; o++) redS[r * WST + o] = oacc[i][o];
        }
    }
    __syncthreads();
    if (wn == 1 && (lane & 3) == 0) {
        #pragma unroll
        for (int i = 0; i < 4; i++) {
            const int r = wm * 32 + (i >> 1) * 16 + (i & 1) * 8 + lm;
            #pragma unroll
            for (int o = 0; o < OUT_DIM; o++) redS[r * WST + o] += oacc[i][o];
        }
    }
    __syncthreads();

    float* pbase = g_part + (size_t)slice * B_ROWS * OUT_DIM + (size_t)m0 * OUT_DIM;
    for (int e = tid; e < TM * OUT_DIM; e += NTHREADS) {
        const int r = e / OUT_DIM;
        const int o = e - r * OUT_DIM;
        pbase[(size_t)r * OUT_DIM + o] = redS[r * WST + o];
    }
}

// ---------------------------------------------------------------------------
// Reduce: out = sum of 8 slice partials + bias
// ---------------------------------------------------------------------------
__global__ void reduce_kernel(const float* __restrict__ bias, float* __restrict__ out) {
    const int i = blockIdx.x * blockDim.x + threadIdx.x;
    if (i >= B_ROWS * OUT_DIM) return;
    const int o = i % OUT_DIM;
    float s = __ldg(&bias[o]);
    #pragma unroll
    for (int sl = 0; sl < NSLICE; sl++)
        s += g_part[(size_t)sl * B_ROWS * OUT_DIM + i];
    out[i] = s;
}

// ---------------------------------------------------------------------------
// Launch
// ---------------------------------------------------------------------------
extern "C" void kernel_launch(void* const* d_in, const int* in_sizes, int n_in,
                              void* d_out, int out_size) {
    const float* x       = (const float*)d_in[0];
    const float* centres = (const float*)d_in[1];
    const float* ls      = (const float*)d_in[2];
    const float* W       = (const float*)d_in[3];
    const float* bias    = (const float*)d_in[4];
    float* out           = (float*)d_out;

    const int nwarps = B_ROWS + C_DIM;              // 18432
    prep_kernel<<<nwarps / 8, 256>>>(x, centres, ls);

    cudaFuncSetAttribute(rbf_mma_kernel,
                         cudaFuncAttributeMaxDynamicSharedMemorySize, SMEM_TOTAL);
    rbf_mma_kernel<<<(B_ROWS / TM) * NSLICE, NTHREADS, SMEM_TOTAL>>>(W);

    reduce_kernel<<<(B_ROWS * OUT_DIM + 255) / 256, 256>>>(bias, out);
}

// round 7
// speedup vs baseline: 2.0364x; 2.0364x over previous
#include <cuda_runtime.h>
#include <cuda_fp8.h>
#include <cstdint>

// ---------------------------------------------------------------------------
// Problem constants
// ---------------------------------------------------------------------------
#define B_ROWS  16384
#define D_DIM   784
#define C_DIM   2048
#define OUT_DIM 10

#define KPAD   800               // 784 padded to 25*32 (fp8 bytes)
#define KWORDS 200               // KPAD/4
#define KB     160               // K bytes per pipeline block
#define NKBLK  5                 // blocks per chunk (5*160 = 800)
#define NK32   5                 // k32 steps per block (160/32)
#define TM     128               // x rows per CTA
#define TN     128               // centres per chunk
#define NSLICE 8                 // C split across CTAs (wave balance)
#define CHPS   2                 // chunks per slice (256 centres)
#define NGBLK  (CHPS * NKBLK)    // 10 blocks per CTA
#define NTHREADS 256

// smem tile stride: 160 data + 16 pad bytes (ldmatrix phases r*11 mod 8: all distinct)
#define ASTB  176
#define TILEB 22528u             // 128 * 176
#define WST   12                 // floats per Wcol row (10 + 2 pad)

// smem byte offsets
#define OFF_A    0u              // 2 x 22528 = 45056
#define OFF_B    45056u          // 2 x 22528 = 45056
#define OFF_WCOL 90112u          // 128 x 12 x 4 = 6144
#define OFF_C2   96256u          // 128 x 4
#define OFF_IS2  96768u
#define SMEM_TOTAL 97280u
#define OFF_RED  OFF_A           // final reduction overlays A buffer

// ---------------------------------------------------------------------------
// Device-global scratch (no allocations allowed)
// ---------------------------------------------------------------------------
__device__ __align__(16) uint32_t g_xq[(size_t)B_ROWS * KWORDS];   // 13.1 MB fp8
__device__ __align__(16) uint32_t g_cq[(size_t)C_DIM * KWORDS];    // 1.6 MB fp8
__device__ float g_x2[B_ROWS];
__device__ float g_c2[C_DIM];
__device__ float g_is2[C_DIM];
__device__ float g_part[(size_t)NSLICE * B_ROWS * OUT_DIM];        // 5.2 MB

// ---------------------------------------------------------------------------
// PTX helpers (base-ISA sm_80/89 era; valid for compute_103 virtual arch)
// ---------------------------------------------------------------------------
__device__ __forceinline__ uint32_t smem_u32(const void* p) {
    uint32_t a;
    asm("{ .reg .u64 t; cvta.to.shared.u64 t, %1; cvt.u32.u64 %0, t; }" : "=r"(a) : "l"(p));
    return a;
}

__device__ __forceinline__ void cp16(uint32_t dst, const void* src) {
    asm volatile("cp.async.cg.shared.global [%0], [%1], 16;" :: "r"(dst), "l"(src));
}
#define CP_COMMIT() asm volatile("cp.async.commit_group;" ::: "memory")
#define CP_WAIT0()  asm volatile("cp.async.wait_group 0;"  ::: "memory")

__device__ __forceinline__ void ldm_x4(uint32_t* r, uint32_t addr) {
    asm volatile("ldmatrix.sync.aligned.m8n8.x4.shared.b16 {%0,%1,%2,%3}, [%4];"
                 : "=r"(r[0]), "=r"(r[1]), "=r"(r[2]), "=r"(r[3]) : "r"(addr));
}

// fp8 e4m3 MMA: m16n8k32, f32 accum (sm_89+ base ISA; full rate on sm_103a SIMT)
__device__ __forceinline__ void mma16832_fp8(float* c, const uint32_t* a, const uint32_t* b) {
    asm volatile(
        "mma.sync.aligned.m16n8k32.row.col.f32.e4m3.e4m3.f32 "
        "{%0,%1,%2,%3}, {%4,%5,%6,%7}, {%8,%9}, {%0,%1,%2,%3};"
        : "+f"(c[0]), "+f"(c[1]), "+f"(c[2]), "+f"(c[3])
        : "r"(a[0]), "r"(a[1]), "r"(a[2]), "r"(a[3]), "r"(b[0]), "r"(b[1]));
}

__device__ __forceinline__ uint32_t quad_to_fp8(float4 v) {
    __nv_fp8x2_storage_t lo = __nv_cvt_float2_to_fp8x2(make_float2(v.x, v.y),
                                                       __NV_SATFINITE, __NV_E4M3);
    __nv_fp8x2_storage_t hi = __nv_cvt_float2_to_fp8x2(make_float2(v.z, v.w),
                                                       __NV_SATFINITE, __NV_E4M3);
    return (uint32_t)lo | ((uint32_t)hi << 16);
}

// ---------------------------------------------------------------------------
// Fused prep: fp8 conversion (padded) + row squared norms. One warp per row;
// handles both x (rows < B_ROWS) and centres.
// ---------------------------------------------------------------------------
__global__ void prep_kernel(const float* __restrict__ x,
                            const float* __restrict__ c,
                            const float* __restrict__ ls) {
    const int gw   = (blockIdx.x * blockDim.x + threadIdx.x) >> 5;
    const int lane = threadIdx.x & 31;
    const bool isX = gw < B_ROWS;
    const int row  = isX ? gw : gw - B_ROWS;
    if (!isX && row >= C_DIM) return;

    const float4* src = (const float4*)((isX ? x : c) + (size_t)row * D_DIM);
    uint32_t* dst = (isX ? g_xq : g_cq) + (size_t)row * KWORDS;

    float s = 0.f;
    #pragma unroll
    for (int i = 0; i < 7; i++) {
        const int w = lane + i * 32;
        if (w < KWORDS) {
            float4 v = (w < D_DIM / 4) ? src[w] : make_float4(0.f, 0.f, 0.f, 0.f);
            s = fmaf(v.x, v.x, fmaf(v.y, v.y, fmaf(v.z, v.z, fmaf(v.w, v.w, s))));
            dst[w] = quad_to_fp8(v);
        }
    }
    #pragma unroll
    for (int m = 16; m; m >>= 1) s += __shfl_xor_sync(0xffffffffu, s, m);
    if (lane == 0) {
        if (isX) g_x2[row] = s;
        else     { g_c2[row] = s; g_is2[row] = __expf(-2.f * ls[row]); }
    }
}

// ---------------------------------------------------------------------------
// Main kernel: fp8 mma, 8-way C-slice, register epilogue with underflow skip
// ---------------------------------------------------------------------------
__global__ __launch_bounds__(NTHREADS, 1)
void rbf_mma_kernel(const float* __restrict__ W) {
    extern __shared__ char sm[];
    const uint32_t sbase = smem_u32(sm);

    const int tid  = threadIdx.x;
    const int wid  = tid >> 5;
    const int lane = tid & 31;
    const int wm   = wid & 3;
    const int wn   = wid >> 2;
    const int lm   = lane >> 2;
    const int ln   = (lane & 3) * 2;

    const int m_tile = blockIdx.x >> 3;
    const int slice  = blockIdx.x & (NSLICE - 1);
    const int m0     = m_tile * TM;
    const int chunk0 = slice * CHPS;

    float* c2S   = (float*)(sm + OFF_C2);
    float* is2S  = (float*)(sm + OFF_IS2);
    float* WcolS = (float*)(sm + OFF_WCOL);

    // per-thread fixed rows
    const int ra0 = m0 + wm * 32 + lm;
    const float x2a0 = g_x2[ra0];
    const float x2b0 = g_x2[ra0 + 8];
    const float x2a1 = g_x2[ra0 + 16];
    const float x2b1 = g_x2[ra0 + 24];

    float oacc[4][OUT_DIM];
    #pragma unroll
    for (int i = 0; i < 4; i++)
        #pragma unroll
        for (int o = 0; o < OUT_DIM; o++) oacc[i][o] = 0.f;

    // preload block g=0 (chunk0, koff 0) into buf 0
    {
        const int n0 = chunk0 * TN;
        #pragma unroll
        for (int i = 0; i < 5; i++) {
            int idx = tid + i * NTHREADS;       // 0..1279
            int r = idx / 10, ch = idx - r * 10;
            cp16(sbase + OFF_A + (uint32_t)r * ASTB + ch * 16,
                 (const char*)(g_xq + (size_t)(m0 + r) * KWORDS) + ch * 16);
            cp16(sbase + OFF_B + (uint32_t)r * ASTB + ch * 16,
                 (const char*)(g_cq + (size_t)(n0 + r) * KWORDS) + ch * 16);
        }
        CP_COMMIT();
    }

    for (int cl = 0; cl < CHPS; cl++) {
        const int chunk = chunk0 + cl;
        const int n0 = chunk * TN;

        if (tid < TN) {
            c2S[tid]  = g_c2[n0 + tid];
            is2S[tid] = g_is2[n0 + tid];
        }
        #pragma unroll
        for (int i = 0; i < 5; i++) {
            int idx = tid + i * NTHREADS;       // TN*OUT = 1280
            int cc = idx / OUT_DIM, o = idx - cc * OUT_DIM;
            WcolS[cc * WST + o] = W[(size_t)o * C_DIM + n0 + cc];
        }

        float acc[2][8][4];
        #pragma unroll
        for (int i = 0; i < 2; i++)
            #pragma unroll
            for (int j = 0; j < 8; j++)
                #pragma unroll
                for (int e = 0; e < 4; e++) acc[i][j][e] = 0.f;

        for (int kb = 0; kb < NKBLK; kb++) {
            const int g   = cl * NKBLK + kb;
            const int buf = g & 1;
            CP_WAIT0();
            __syncthreads();

            if (g + 1 < NGBLK) {
                const int gn   = g + 1;
                const int ncl  = gn / NKBLK;
                const int nkb  = gn - ncl * NKBLK;
                const int nn0  = (chunk0 + ncl) * TN;
                const int koff = nkb * KB;
                const uint32_t obuf = (uint32_t)(gn & 1) * TILEB;
                #pragma unroll
                for (int i = 0; i < 5; i++) {
                    int idx = tid + i * NTHREADS;
                    int r = idx / 10, ch = idx - r * 10;
                    cp16(sbase + OFF_A + obuf + (uint32_t)r * ASTB + ch * 16,
                         (const char*)(g_xq + (size_t)(m0 + r) * KWORDS) + koff + ch * 16);
                    cp16(sbase + OFF_B + obuf + (uint32_t)r * ASTB + ch * 16,
                         (const char*)(g_cq + (size_t)(nn0 + r) * KWORDS) + koff + ch * 16);
                }
                CP_COMMIT();
            }

            const uint32_t aBase = sbase + OFF_A + (uint32_t)buf * TILEB;
            const uint32_t bBase = sbase + OFF_B + (uint32_t)buf * TILEB;
            const uint32_t lrow  = (uint32_t)(lane & 15);
            const uint32_t lcol  = (uint32_t)(lane >> 4) * 16u;

            #pragma unroll
            for (int ks = 0; ks < NK32; ks++) {
                uint32_t af[2][4];
                #pragma unroll
                for (int mi = 0; mi < 2; mi++)
                    ldm_x4(af[mi], aBase + (uint32_t)(wm * 32 + mi * 16 + lrow) * ASTB
                                         + (uint32_t)ks * 32u + lcol);
                uint32_t bf[8][2];
                #pragma unroll
                for (int njj = 0; njj < 4; njj++) {
                    uint32_t r4[4];
                    ldm_x4(r4, bBase + (uint32_t)(wn * 64 + njj * 16 + lrow) * ASTB
                                     + (uint32_t)ks * 32u + lcol);
                    bf[njj * 2 + 0][0] = r4[0];
                    bf[njj * 2 + 1][0] = r4[1];
                    bf[njj * 2 + 0][1] = r4[2];
                    bf[njj * 2 + 1][1] = r4[3];
                }
                #pragma unroll
                for (int mi = 0; mi < 2; mi++)
                    #pragma unroll
                    for (int nf = 0; nf < 8; nf++)
                        mma16832_fp8(acc[mi][nf], af[mi], bf[nf]);
            }
        }

        // ---- register epilogue: t = d2*is2; exp(-t)==0 exactly for t>104 ----
        #pragma unroll
        for (int nf = 0; nf < 8; nf++) {
            const int c0 = wn * 64 + nf * 8 + ln;
            const int c1 = c0 + 1;
            const float cc0 = c2S[c0],  cc1 = c2S[c1];
            const float ii0 = is2S[c0], ii1 = is2S[c1];
            #pragma unroll
            for (int mi = 0; mi < 2; mi++) {
                const float xa = mi ? x2a1 : x2a0;
                const float xb = mi ? x2b1 : x2b0;
                const float t00 = fmaxf(xa + cc0 - 2.f * acc[mi][nf][0], 0.f) * ii0;
                const float t01 = fmaxf(xa + cc1 - 2.f * acc[mi][nf][1], 0.f) * ii1;
                const float t10 = fmaxf(xb + cc0 - 2.f * acc[mi][nf][2], 0.f) * ii0;
                const float t11 = fmaxf(xb + cc1 - 2.f * acc[mi][nf][3], 0.f) * ii1;
                if (t00 < 104.f || t01 < 104.f || t10 < 104.f || t11 < 104.f) {
                    const float p00 = __expf(-t00);
                    const float p01 = __expf(-t01);
                    const float p10 = __expf(-t10);
                    const float p11 = __expf(-t11);
                    #pragma unroll
                    for (int o = 0; o < OUT_DIM; o++) {
                        const float w0 = WcolS[c0 * WST + o];
                        const float w1 = WcolS[c1 * WST + o];
                        oacc[mi * 2 + 0][o] = fmaf(p00, w0, fmaf(p01, w1, oacc[mi * 2 + 0][o]));
                        oacc[mi * 2 + 1][o] = fmaf(p10, w0, fmaf(p11, w1, oacc[mi * 2 + 1][o]));
                    }
                }
            }
        }
        __syncthreads();   // meta consumed before next chunk overwrites
    }

    // ---- in-CTA reduction, write partial buffer (no atomics) ----
    #pragma unroll
    for (int i = 0; i < 4; i++)
        #pragma unroll
        for (int o = 0; o < OUT_DIM; o++) {
            float v = oacc[i][o];
            v += __shfl_xor_sync(0xffffffffu, v, 1);
            v += __shfl_xor_sync(0xffffffffu, v, 2);
            oacc[i][o] = v;
        }

    float* redS = (float*)(sm + OFF_RED);
    if (wn == 0 && (lane & 3) == 0) {
        #pragma unroll
        for (int i = 0; i < 4; i++) {
            const int r = wm * 32 + (i >> 1) * 16 + (i & 1) * 8 + lm;
            #pragma unroll
            for (int o = 0; o < OUT_DIM; o++) redS[r * WST + o] = oacc[i][o];
        }
    }
    __syncthreads();
    if (wn == 1 && (lane & 3) == 0) {
        #pragma unroll
        for (int i = 0; i < 4; i++) {
            const int r = wm * 32 + (i >> 1) * 16 + (i & 1) * 8 + lm;
            #pragma unroll
            for (int o = 0; o < OUT_DIM; o++) redS[r * WST + o] += oacc[i][o];
        }
    }
    __syncthreads();

    float* pbase = g_part + (size_t)slice * B_ROWS * OUT_DIM + (size_t)m0 * OUT_DIM;
    for (int e = tid; e < TM * OUT_DIM; e += NTHREADS) {
        const int r = e / OUT_DIM;
        const int o = e - r * OUT_DIM;
        pbase[(size_t)r * OUT_DIM + o] = redS[r * WST + o];
    }
}

// ---------------------------------------------------------------------------
// Reduce: out = sum of 8 slice partials + bias
// ---------------------------------------------------------------------------
__global__ void reduce_kernel(const float* __restrict__ bias, float* __restrict__ out) {
    const int i = blockIdx.x * blockDim.x + threadIdx.x;
    if (i >= B_ROWS * OUT_DIM) return;
    const int o = i % OUT_DIM;
    float s = __ldg(&bias[o]);
    #pragma unroll
    for (int sl = 0; sl < NSLICE; sl++)
        s += g_part[(size_t)sl * B_ROWS * OUT_DIM + i];
    out[i] = s;
}

// ---------------------------------------------------------------------------
// Launch
// ---------------------------------------------------------------------------
extern "C" void kernel_launch(void* const* d_in, const int* in_sizes, int n_in,
                              void* d_out, int out_size) {
    const float* x       = (const float*)d_in[0];
    const float* centres = (const float*)d_in[1];
    const float* ls      = (const float*)d_in[2];
    const float* W       = (const float*)d_in[3];
    const float* bias    = (const float*)d_in[4];
    float* out           = (float*)d_out;

    const int nwarps = B_ROWS + C_DIM;              // 18432
    prep_kernel<<<nwarps / 8, 256>>>(x, centres, ls);

    cudaFuncSetAttribute(rbf_mma_kernel,
                         cudaFuncAttributeMaxDynamicSharedMemorySize, SMEM_TOTAL);
    rbf_mma_kernel<<<(B_ROWS / TM) * NSLICE, NTHREADS, SMEM_TOTAL>>>(W);

    reduce_kernel<<<(B_ROWS * OUT_DIM + 255) / 256, 256>>>(bias, out);
}

// round 8
// speedup vs baseline: 2.0379x; 1.0007x over previous
#include <cuda_runtime.h>
#include <cuda_fp8.h>
#include <cstdint>

// ---------------------------------------------------------------------------
// Problem constants
// ---------------------------------------------------------------------------
#define B_ROWS  16384
#define D_DIM   784
#define C_DIM   2048
#define OUT_DIM 10

#define KPAD   800               // 784 padded to 25*32 (fp8 bytes)
#define KWORDS 200               // KPAD/4
#define KB     160               // K bytes per pipeline block
#define NKBLK  5                 // blocks per chunk (5*160 = 800)
#define NK32   5                 // k32 steps per block (160/32)
#define TM     128               // x rows per CTA
#define TN     128               // centres per chunk
#define NSLICE 8                 // C split across CTAs (wave balance)
#define CHPS   2                 // chunks per slice (256 centres)
#define NGBLK  (CHPS * NKBLK)    // 10 blocks per CTA
#define NTHREADS 256

// smem tile stride: 160 data + 16 pad bytes (ldmatrix phases r*11 mod 8: all distinct)
#define ASTB  176
#define TILEB 22528u             // 128 * 176
#define WST   12                 // floats per Wcol row (10 + 2 pad)

// smem byte offsets
#define OFF_A    0u              // 2 x 22528 = 45056
#define OFF_B    45056u          // 2 x 22528 = 45056
#define OFF_WCOL 90112u          // 128 x 12 x 4 = 6144
#define OFF_C2   96256u          // 128 x 4
#define OFF_IS2  96768u
#define SMEM_TOTAL 97280u
#define OFF_RED  OFF_A           // final reduction overlays A buffer

// ---------------------------------------------------------------------------
// Device-global scratch (no allocations allowed)
// ---------------------------------------------------------------------------
__device__ __align__(16) uint32_t g_xq[(size_t)B_ROWS * KWORDS];   // 13.1 MB fp8
__device__ __align__(16) uint32_t g_cq[(size_t)C_DIM * KWORDS];    // 1.6 MB fp8
__device__ float g_x2[B_ROWS];
__device__ float g_c2[C_DIM];
__device__ float g_is2[C_DIM];
__device__ __align__(16) float g_part[(size_t)NSLICE * B_ROWS * OUT_DIM]; // 5.2 MB

// ---------------------------------------------------------------------------
// PTX helpers (base-ISA sm_80/89 era; valid for compute_103 virtual arch)
// ---------------------------------------------------------------------------
__device__ __forceinline__ uint32_t smem_u32(const void* p) {
    uint32_t a;
    asm("{ .reg .u64 t; cvta.to.shared.u64 t, %1; cvt.u32.u64 %0, t; }" : "=r"(a) : "l"(p));
    return a;
}

__device__ __forceinline__ void cp16(uint32_t dst, const void* src) {
    asm volatile("cp.async.cg.shared.global [%0], [%1], 16;" :: "r"(dst), "l"(src));
}
#define CP_COMMIT() asm volatile("cp.async.commit_group;" ::: "memory")
#define CP_WAIT0()  asm volatile("cp.async.wait_group 0;"  ::: "memory")

__device__ __forceinline__ void ldm_x4(uint32_t* r, uint32_t addr) {
    asm volatile("ldmatrix.sync.aligned.m8n8.x4.shared.b16 {%0,%1,%2,%3}, [%4];"
                 : "=r"(r[0]), "=r"(r[1]), "=r"(r[2]), "=r"(r[3]) : "r"(addr));
}

// fp8 e4m3 MMA: m16n8k32, f32 accum (sm_89+ base ISA; full rate on sm_103a SIMT)
__device__ __forceinline__ void mma16832_fp8(float* c, const uint32_t* a, const uint32_t* b) {
    asm volatile(
        "mma.sync.aligned.m16n8k32.row.col.f32.e4m3.e4m3.f32 "
        "{%0,%1,%2,%3}, {%4,%5,%6,%7}, {%8,%9}, {%0,%1,%2,%3};"
        : "+f"(c[0]), "+f"(c[1]), "+f"(c[2]), "+f"(c[3])
        : "r"(a[0]), "r"(a[1]), "r"(a[2]), "r"(a[3]), "r"(b[0]), "r"(b[1]));
}

__device__ __forceinline__ uint32_t quad_to_fp8(float4 v) {
    __nv_fp8x2_storage_t lo = __nv_cvt_float2_to_fp8x2(make_float2(v.x, v.y),
                                                       __NV_SATFINITE, __NV_E4M3);
    __nv_fp8x2_storage_t hi = __nv_cvt_float2_to_fp8x2(make_float2(v.z, v.w),
                                                       __NV_SATFINITE, __NV_E4M3);
    return (uint32_t)lo | ((uint32_t)hi << 16);
}

// ---------------------------------------------------------------------------
// Fused prep: fp8 conversion (padded) + row squared norms. One warp per row;
// handles both x (rows < B_ROWS) and centres.
// ---------------------------------------------------------------------------
__global__ __launch_bounds__(256)
void prep_kernel(const float* __restrict__ x,
                 const float* __restrict__ c,
                 const float* __restrict__ ls) {
    const int gw   = (blockIdx.x * blockDim.x + threadIdx.x) >> 5;
    const int lane = threadIdx.x & 31;
    const bool isX = gw < B_ROWS;
    const int row  = isX ? gw : gw - B_ROWS;
    if (!isX && row >= C_DIM) return;

    const float4* src = (const float4*)((isX ? x : c) + (size_t)row * D_DIM);
    uint32_t* dst = (isX ? g_xq : g_cq) + (size_t)row * KWORDS;

    // 196 data words + 4 pad words. 6 full warp-iterations (192 words), then
    // a uniform tail: lanes 0..7 cover words 192..199 (196..199 zero-padded).
    float4 v[7];
    #pragma unroll
    for (int i = 0; i < 6; i++) v[i] = src[lane + i * 32];
    const int wt = 192 + lane;
    v[6] = (lane < 4) ? src[wt] : make_float4(0.f, 0.f, 0.f, 0.f);

    float s = 0.f;
    #pragma unroll
    for (int i = 0; i < 7; i++)
        s = fmaf(v[i].x, v[i].x, fmaf(v[i].y, v[i].y,
            fmaf(v[i].z, v[i].z, fmaf(v[i].w, v[i].w, s))));

    #pragma unroll
    for (int i = 0; i < 6; i++) dst[lane + i * 32] = quad_to_fp8(v[i]);
    if (lane < 8) dst[wt] = quad_to_fp8(v[6]);   // words 196..199 write zeros

    #pragma unroll
    for (int m = 16; m; m >>= 1) s += __shfl_xor_sync(0xffffffffu, s, m);
    if (lane == 0) {
        if (isX) g_x2[row] = s;
        else     { g_c2[row] = s; g_is2[row] = __expf(-2.f * ls[row]); }
    }
}

// ---------------------------------------------------------------------------
// Main kernel: fp8 mma, 8-way C-slice, register epilogue with underflow skip
// (unchanged from R7 — measured at >=99% of the SIMT fp8 tensor ceiling)
// ---------------------------------------------------------------------------
__global__ __launch_bounds__(NTHREADS, 1)
void rbf_mma_kernel(const float* __restrict__ W) {
    extern __shared__ char sm[];
    const uint32_t sbase = smem_u32(sm);

    const int tid  = threadIdx.x;
    const int wid  = tid >> 5;
    const int lane = tid & 31;
    const int wm   = wid & 3;
    const int wn   = wid >> 2;
    const int lm   = lane >> 2;
    const int ln   = (lane & 3) * 2;

    const int m_tile = blockIdx.x >> 3;
    const int slice  = blockIdx.x & (NSLICE - 1);
    const int m0     = m_tile * TM;
    const int chunk0 = slice * CHPS;

    float* c2S   = (float*)(sm + OFF_C2);
    float* is2S  = (float*)(sm + OFF_IS2);
    float* WcolS = (float*)(sm + OFF_WCOL);

    const int ra0 = m0 + wm * 32 + lm;
    const float x2a0 = g_x2[ra0];
    const float x2b0 = g_x2[ra0 + 8];
    const float x2a1 = g_x2[ra0 + 16];
    const float x2b1 = g_x2[ra0 + 24];

    float oacc[4][OUT_DIM];
    #pragma unroll
    for (int i = 0; i < 4; i++)
        #pragma unroll
        for (int o = 0; o < OUT_DIM; o++) oacc[i][o] = 0.f;

    // preload block g=0 (chunk0, koff 0) into buf 0
    {
        const int n0 = chunk0 * TN;
        #pragma unroll
        for (int i = 0; i < 5; i++) {
            int idx = tid + i * NTHREADS;       // 0..1279
            int r = idx / 10, ch = idx - r * 10;
            cp16(sbase + OFF_A + (uint32_t)r * ASTB + ch * 16,
                 (const char*)(g_xq + (size_t)(m0 + r) * KWORDS) + ch * 16);
            cp16(sbase + OFF_B + (uint32_t)r * ASTB + ch * 16,
                 (const char*)(g_cq + (size_t)(n0 + r) * KWORDS) + ch * 16);
        }
        CP_COMMIT();
    }

    for (int cl = 0; cl < CHPS; cl++) {
        const int chunk = chunk0 + cl;
        const int n0 = chunk * TN;

        if (tid < TN) {
            c2S[tid]  = g_c2[n0 + tid];
            is2S[tid] = g_is2[n0 + tid];
        }
        #pragma unroll
        for (int i = 0; i < 5; i++) {
            int idx = tid + i * NTHREADS;       // TN*OUT = 1280
            int cc = idx / OUT_DIM, o = idx - cc * OUT_DIM;
            WcolS[cc * WST + o] = W[(size_t)o * C_DIM + n0 + cc];
        }

        float acc[2][8][4];
        #pragma unroll
        for (int i = 0; i < 2; i++)
            #pragma unroll
            for (int j = 0; j < 8; j++)
                #pragma unroll
                for (int e = 0; e < 4; e++) acc[i][j][e] = 0.f;

        for (int kb = 0; kb < NKBLK; kb++) {
            const int g   = cl * NKBLK + kb;
            const int buf = g & 1;
            CP_WAIT0();
            __syncthreads();

            if (g + 1 < NGBLK) {
                const int gn   = g + 1;
                const int ncl  = gn / NKBLK;
                const int nkb  = gn - ncl * NKBLK;
                const int nn0  = (chunk0 + ncl) * TN;
                const int koff = nkb * KB;
                const uint32_t obuf = (uint32_t)(gn & 1) * TILEB;
                #pragma unroll
                for (int i = 0; i < 5; i++) {
                    int idx = tid + i * NTHREADS;
                    int r = idx / 10, ch = idx - r * 10;
                    cp16(sbase + OFF_A + obuf + (uint32_t)r * ASTB + ch * 16,
                         (const char*)(g_xq + (size_t)(m0 + r) * KWORDS) + koff + ch * 16);
                    cp16(sbase + OFF_B + obuf + (uint32_t)r * ASTB + ch * 16,
                         (const char*)(g_cq + (size_t)(nn0 + r) * KWORDS) + koff + ch * 16);
                }
                CP_COMMIT();
            }

            const uint32_t aBase = sbase + OFF_A + (uint32_t)buf * TILEB;
            const uint32_t bBase = sbase + OFF_B + (uint32_t)buf * TILEB;
            const uint32_t lrow  = (uint32_t)(lane & 15);
            const uint32_t lcol  = (uint32_t)(lane >> 4) * 16u;

            #pragma unroll
            for (int ks = 0; ks < NK32; ks++) {
                uint32_t af[2][4];
                #pragma unroll
                for (int mi = 0; mi < 2; mi++)
                    ldm_x4(af[mi], aBase + (uint32_t)(wm * 32 + mi * 16 + lrow) * ASTB
                                         + (uint32_t)ks * 32u + lcol);
                uint32_t bf[8][2];
                #pragma unroll
                for (int njj = 0; njj < 4; njj++) {
                    uint32_t r4[4];
                    ldm_x4(r4, bBase + (uint32_t)(wn * 64 + njj * 16 + lrow) * ASTB
                                     + (uint32_t)ks * 32u + lcol);
                    bf[njj * 2 + 0][0] = r4[0];
                    bf[njj * 2 + 1][0] = r4[1];
                    bf[njj * 2 + 0][1] = r4[2];
                    bf[njj * 2 + 1][1] = r4[3];
                }
                #pragma unroll
                for (int mi = 0; mi < 2; mi++)
                    #pragma unroll
                    for (int nf = 0; nf < 8; nf++)
                        mma16832_fp8(acc[mi][nf], af[mi], bf[nf]);
            }
        }

        // ---- register epilogue: t = d2*is2; exp(-t)==0 exactly for t>104 ----
        #pragma unroll
        for (int nf = 0; nf < 8; nf++) {
            const int c0 = wn * 64 + nf * 8 + ln;
            const int c1 = c0 + 1;
            const float cc0 = c2S[c0],  cc1 = c2S[c1];
            const float ii0 = is2S[c0], ii1 = is2S[c1];
            #pragma unroll
            for (int mi = 0; mi < 2; mi++) {
                const float xa = mi ? x2a1 : x2a0;
                const float xb = mi ? x2b1 : x2b0;
                const float t00 = fmaxf(xa + cc0 - 2.f * acc[mi][nf][0], 0.f) * ii0;
                const float t01 = fmaxf(xa + cc1 - 2.f * acc[mi][nf][1], 0.f) * ii1;
                const float t10 = fmaxf(xb + cc0 - 2.f * acc[mi][nf][2], 0.f) * ii0;
                const float t11 = fmaxf(xb + cc1 - 2.f * acc[mi][nf][3], 0.f) * ii1;
                if (t00 < 104.f || t01 < 104.f || t10 < 104.f || t11 < 104.f) {
                    const float p00 = __expf(-t00);
                    const float p01 = __expf(-t01);
                    const float p10 = __expf(-t10);
                    const float p11 = __expf(-t11);
                    #pragma unroll
                    for (int o = 0; o < OUT_DIM; o++) {
                        const float w0 = WcolS[c0 * WST + o];
                        const float w1 = WcolS[c1 * WST + o];
                        oacc[mi * 2 + 0][o] = fmaf(p00, w0, fmaf(p01, w1, oacc[mi * 2 + 0][o]));
                        oacc[mi * 2 + 1][o] = fmaf(p10, w0, fmaf(p11, w1, oacc[mi * 2 + 1][o]));
                    }
                }
            }
        }
        __syncthreads();   // meta consumed before next chunk overwrites
    }

    // ---- in-CTA reduction, write partial buffer (no atomics) ----
    #pragma unroll
    for (int i = 0; i < 4; i++)
        #pragma unroll
        for (int o = 0; o < OUT_DIM; o++) {
            float v = oacc[i][o];
            v += __shfl_xor_sync(0xffffffffu, v, 1);
            v += __shfl_xor_sync(0xffffffffu, v, 2);
            oacc[i][o] = v;
        }

    float* redS = (float*)(sm + OFF_RED);
    if (wn == 0 && (lane & 3) == 0) {
        #pragma unroll
        for (int i = 0; i < 4; i++) {
            const int r = wm * 32 + (i >> 1) * 16 + (i & 1) * 8 + lm;
            #pragma unroll
            for (int o = 0; o < OUT_DIM; o++) redS[r * WST + o] = oacc[i][o];
        }
    }
    __syncthreads();
    if (wn == 1 && (lane & 3) == 0) {
        #pragma unroll
        for (int i = 0; i < 4; i++) {
            const int r = wm * 32 + (i >> 1) * 16 + (i & 1) * 8 + lm;
            #pragma unroll
            for (int o = 0; o < OUT_DIM; o++) redS[r * WST + o] += oacc[i][o];
        }
    }
    __syncthreads();

    float* pbase = g_part + (size_t)slice * B_ROWS * OUT_DIM + (size_t)m0 * OUT_DIM;
    for (int e = tid; e < TM * OUT_DIM; e += NTHREADS) {
        const int r = e / OUT_DIM;
        const int o = e - r * OUT_DIM;
        pbase[(size_t)r * OUT_DIM + o] = redS[r * WST + o];
    }
}

// ---------------------------------------------------------------------------
// Reduce: out = sum of 8 slice partials + bias  (float4 vectorized)
// ---------------------------------------------------------------------------
__global__ void reduce_kernel(const float* __restrict__ bias, float* __restrict__ out) {
    const int t = blockIdx.x * blockDim.x + threadIdx.x;       // float4 index
    const int NQ = (B_ROWS * OUT_DIM) / 4;                     // 40960
    if (t >= NQ) return;
    const int i0 = t * 4;
    float4 s;
    s.x = __ldg(&bias[(i0 + 0) % OUT_DIM]);
    s.y = __ldg(&bias[(i0 + 1) % OUT_DIM]);
    s.z = __ldg(&bias[(i0 + 2) % OUT_DIM]);
    s.w = __ldg(&bias[(i0 + 3) % OUT_DIM]);
    #pragma unroll
    for (int sl = 0; sl < NSLICE; sl++) {
        const float4 p = *(const float4*)&g_part[(size_t)sl * B_ROWS * OUT_DIM + i0];
        s.x += p.x; s.y += p.y; s.z += p.z; s.w += p.w;
    }
    ((float4*)out)[t] = s;
}

// ---------------------------------------------------------------------------
// Launch
// ---------------------------------------------------------------------------
extern "C" void kernel_launch(void* const* d_in, const int* in_sizes, int n_in,
                              void* d_out, int out_size) {
    const float* x       = (const float*)d_in[0];
    const float* centres = (const float*)d_in[1];
    const float* ls      = (const float*)d_in[2];
    const float* W       = (const float*)d_in[3];
    const float* bias    = (const float*)d_in[4];
    float* out           = (float*)d_out;

    const int nwarps = B_ROWS + C_DIM;              // 18432
    prep_kernel<<<nwarps / 8, 256>>>(x, centres, ls);

    cudaFuncSetAttribute(rbf_mma_kernel,
                         cudaFuncAttributeMaxDynamicSharedMemorySize, SMEM_TOTAL);
    rbf_mma_kernel<<<(B_ROWS / TM) * NSLICE, NTHREADS, SMEM_TOTAL>>>(W);

    reduce_kernel<<<((B_ROWS * OUT_DIM) / 4 + 255) / 256, 256>>>(bias, out);
}

// round 9
// speedup vs baseline: 2.1179x; 1.0392x over previous
#include <cuda_runtime.h>
#include <cuda_fp8.h>
#include <cstdint>

// ---------------------------------------------------------------------------
// Problem constants
// ---------------------------------------------------------------------------
#define B_ROWS  16384
#define D_DIM   784
#define C_DIM   2048
#define OUT_DIM 10

#define KPAD   800               // 784 padded to 25*32 (fp8 bytes)
#define KWORDS 200               // KPAD/4
#define KB     160               // K bytes per pipeline block
#define NKBLK  5                 // blocks per chunk (5*160 = 800)
#define NK32   5                 // k32 steps per block
#define TM     128               // x rows per unit
#define TN     128               // centres per chunk
#define NSLICE 8                 // C split across units
#define CHPS   2                 // chunks per unit (256 centres)
#define BPU    (CHPS * NKBLK)    // 10 blocks per unit
#define NUNITS ((B_ROWS / TM) * NSLICE)   // 1024 work units
#define NTHREADS 256

// smem tile stride: 160 data + 16 pad bytes (ldmatrix phases r*11 mod 8 distinct)
#define ASTB  176
#define TILEB 22528u             // 128 * 176
#define NSTAGE 3
#define WST   12                 // floats per Wcol row (10 + 2 pad)

// smem byte offsets
#define OFF_A    0u                       // 3 x 22528 = 67584
#define OFF_B    67584u                   // 3 x 22528 = 67584
#define OFF_WCOL 135168u                  // 128 x 12 x 4 = 6144
#define OFF_C2   141312u                  // 128 x 4
#define OFF_IS2  141824u
#define OFF_RED  142336u                  // 128 x 12 x 4 = 6144 (separate now)
#define SMEM_TOTAL 148480u

// ---------------------------------------------------------------------------
// Device-global scratch (no allocations allowed)
// ---------------------------------------------------------------------------
__device__ __align__(16) uint32_t g_xq[(size_t)B_ROWS * KWORDS];   // 13.1 MB fp8
__device__ __align__(16) uint32_t g_cq[(size_t)C_DIM * KWORDS];    // 1.6 MB fp8
__device__ float g_x2[B_ROWS];
__device__ float g_c2[C_DIM];
__device__ float g_is2[C_DIM];
__device__ __align__(16) float g_part[(size_t)NSLICE * B_ROWS * OUT_DIM]; // 5.2 MB

// ---------------------------------------------------------------------------
// PTX helpers (base-ISA sm_80/89 era; valid for compute_103 virtual arch)
// ---------------------------------------------------------------------------
__device__ __forceinline__ uint32_t smem_u32(const void* p) {
    uint32_t a;
    asm("{ .reg .u64 t; cvta.to.shared.u64 t, %1; cvt.u32.u64 %0, t; }" : "=r"(a) : "l"(p));
    return a;
}

__device__ __forceinline__ void cp16(uint32_t dst, const void* src) {
    asm volatile("cp.async.cg.shared.global [%0], [%1], 16;" :: "r"(dst), "l"(src));
}
#define CP_COMMIT() asm volatile("cp.async.commit_group;" ::: "memory")
#define CP_WAIT0()  asm volatile("cp.async.wait_group 0;"  ::: "memory")
#define CP_WAIT1()  asm volatile("cp.async.wait_group 1;"  ::: "memory")

__device__ __forceinline__ void ldm_x4(uint32_t* r, uint32_t addr) {
    asm volatile("ldmatrix.sync.aligned.m8n8.x4.shared.b16 {%0,%1,%2,%3}, [%4];"
                 : "=r"(r[0]), "=r"(r[1]), "=r"(r[2]), "=r"(r[3]) : "r"(addr));
}

// fp8 e4m3 MMA: m16n8k32, f32 accum (sm_89+ base ISA; full rate on sm_103a SIMT)
__device__ __forceinline__ void mma16832_fp8(float* c, const uint32_t* a, const uint32_t* b) {
    asm volatile(
        "mma.sync.aligned.m16n8k32.row.col.f32.e4m3.e4m3.f32 "
        "{%0,%1,%2,%3}, {%4,%5,%6,%7}, {%8,%9}, {%0,%1,%2,%3};"
        : "+f"(c[0]), "+f"(c[1]), "+f"(c[2]), "+f"(c[3])
        : "r"(a[0]), "r"(a[1]), "r"(a[2]), "r"(a[3]), "r"(b[0]), "r"(b[1]));
}

__device__ __forceinline__ uint32_t quad_to_fp8(float4 v) {
    __nv_fp8x2_storage_t lo = __nv_cvt_float2_to_fp8x2(make_float2(v.x, v.y),
                                                       __NV_SATFINITE, __NV_E4M3);
    __nv_fp8x2_storage_t hi = __nv_cvt_float2_to_fp8x2(make_float2(v.z, v.w),
                                                       __NV_SATFINITE, __NV_E4M3);
    return (uint32_t)lo | ((uint32_t)hi << 16);
}

// ---------------------------------------------------------------------------
// Fused prep: fp8 conversion (padded) + row squared norms. One warp per row.
// ---------------------------------------------------------------------------
__global__ __launch_bounds__(256)
void prep_kernel(const float* __restrict__ x,
                 const float* __restrict__ c,
                 const float* __restrict__ ls) {
    const int gw   = (blockIdx.x * blockDim.x + threadIdx.x) >> 5;
    const int lane = threadIdx.x & 31;
    const bool isX = gw < B_ROWS;
    const int row  = isX ? gw : gw - B_ROWS;
    if (!isX && row >= C_DIM) return;

    const float4* src = (const float4*)((isX ? x : c) + (size_t)row * D_DIM);
    uint32_t* dst = (isX ? g_xq : g_cq) + (size_t)row * KWORDS;

    float4 v[7];
    #pragma unroll
    for (int i = 0; i < 6; i++) v[i] = src[lane + i * 32];
    const int wt = 192 + lane;
    v[6] = (lane < 4) ? src[wt] : make_float4(0.f, 0.f, 0.f, 0.f);

    float s = 0.f;
    #pragma unroll
    for (int i = 0; i < 7; i++)
        s = fmaf(v[i].x, v[i].x, fmaf(v[i].y, v[i].y,
            fmaf(v[i].z, v[i].z, fmaf(v[i].w, v[i].w, s))));

    #pragma unroll
    for (int i = 0; i < 6; i++) dst[lane + i * 32] = quad_to_fp8(v[i]);
    if (lane < 8) dst[wt] = quad_to_fp8(v[6]);

    #pragma unroll
    for (int m = 16; m; m >>= 1) s += __shfl_xor_sync(0xffffffffu, s, m);
    if (lane == 0) {
        if (isX) g_x2[row] = s;
        else     { g_c2[row] = s; g_is2[row] = __expf(-2.f * ls[row]); }
    }
}

// ---------------------------------------------------------------------------
// Per-block address helper for the flattened persistent pipeline
// gb (per-CTA block idx) -> unit/chunk/kblock -> global tile addresses
// ---------------------------------------------------------------------------
struct BlkA { int m0, n0, koff, kb, cl, unit; };
__device__ __forceinline__ BlkA blk_addr(int gb, int cta, int stride) {
    BlkA b;
    const int ui  = gb / BPU;
    const int rem = gb - ui * BPU;
    b.cl   = rem / NKBLK;
    b.kb   = rem - b.cl * NKBLK;
    b.unit = cta + ui * stride;
    b.m0   = (b.unit >> 3) * TM;
    b.n0   = ((b.unit & (NSLICE - 1)) * CHPS + b.cl) * TN;
    b.koff = b.kb * KB;
    return b;
}

__device__ __forceinline__ void issue_tile(uint32_t sbase, int buf, const BlkA& b, int tid) {
    const uint32_t aOff = OFF_A + (uint32_t)buf * TILEB;
    const uint32_t bOff = OFF_B + (uint32_t)buf * TILEB;
    #pragma unroll
    for (int i = 0; i < 5; i++) {
        int idx = tid + i * NTHREADS;        // 0..1279
        int r = idx / 10, ch = idx - r * 10;
        cp16(sbase + aOff + (uint32_t)r * ASTB + ch * 16,
             (const char*)(g_xq + (size_t)(b.m0 + r) * KWORDS) + b.koff + ch * 16);
        cp16(sbase + bOff + (uint32_t)r * ASTB + ch * 16,
             (const char*)(g_cq + (size_t)(b.n0 + r) * KWORDS) + b.koff + ch * 16);
    }
    CP_COMMIT();
}

// ---------------------------------------------------------------------------
// Persistent main kernel: fp8 mma, 3-stage cp.async pipeline continuous
// across work-unit boundaries; register epilogue with exact underflow skip
// ---------------------------------------------------------------------------
__global__ __launch_bounds__(NTHREADS, 1)
void rbf_mma_kernel(const float* __restrict__ W) {
    extern __shared__ char sm[];
    const uint32_t sbase = smem_u32(sm);

    const int tid  = threadIdx.x;
    const int wid  = tid >> 5;
    const int lane = tid & 31;
    const int wm   = wid & 3;
    const int wn   = wid >> 2;
    const int lm   = lane >> 2;
    const int ln   = (lane & 3) * 2;
    const int cta  = blockIdx.x;
    const int strd = gridDim.x;

    float* c2S   = (float*)(sm + OFF_C2);
    float* is2S  = (float*)(sm + OFF_IS2);
    float* WcolS = (float*)(sm + OFF_WCOL);
    float* redS  = (float*)(sm + OFF_RED);

    // number of units / blocks for this CTA
    const int n_units = (NUNITS - cta + strd - 1) / strd;
    const int NB = n_units * BPU;
    if (n_units <= 0) return;

    // prologue: 2 tiles in flight
    issue_tile(sbase, 0, blk_addr(0, cta, strd), tid);
    if (NB > 1) issue_tile(sbase, 1, blk_addr(1, cta, strd), tid);

    float oacc[4][OUT_DIM];
    #pragma unroll
    for (int i = 0; i < 4; i++)
        #pragma unroll
        for (int o = 0; o < OUT_DIM; o++) oacc[i][o] = 0.f;

    float acc[2][8][4];
    float x2a0 = 0.f, x2b0 = 0.f, x2a1 = 0.f, x2b1 = 0.f;

    for (int gb = 0; gb < NB; gb++) {
        const BlkA b = blk_addr(gb, cta, strd);
        const int buf = gb % NSTAGE;

        if (b.kb == 0) {
            // chunk metadata (prev epilogue's trailing sync protects these)
            if (b.cl == 0) {
                const int ra0 = b.m0 + wm * 32 + lm;
                x2a0 = g_x2[ra0];      x2b0 = g_x2[ra0 + 8];
                x2a1 = g_x2[ra0 + 16]; x2b1 = g_x2[ra0 + 24];
            }
            if (tid < TN) {
                c2S[tid]  = g_c2[b.n0 + tid];
                is2S[tid] = g_is2[b.n0 + tid];
            }
            #pragma unroll
            for (int i = 0; i < 5; i++) {
                int idx = tid + i * NTHREADS;      // TN*OUT = 1280
                int cc = idx / OUT_DIM, o = idx - cc * OUT_DIM;
                WcolS[cc * WST + o] = W[(size_t)o * C_DIM + b.n0 + cc];
            }
            #pragma unroll
            for (int i = 0; i < 2; i++)
                #pragma unroll
                for (int j = 0; j < 8; j++)
                    #pragma unroll
                    for (int e = 0; e < 4; e++) acc[i][j][e] = 0.f;
        }

        // wait for tile gb: committed groups = min(gb+2, NB); allow pending
        // = committed - (gb+1) = 1 normally, 0 on the final block.
        if (gb + 2 <= NB - 1 + 1 && gb + 1 < NB) CP_WAIT1(); else CP_WAIT0();
        __syncthreads();   // tile + metadata visible CTA-wide

        // prefetch tile gb+2
        if (gb + 2 < NB)
            issue_tile(sbase, (gb + 2) % NSTAGE, blk_addr(gb + 2, cta, strd), tid);

        const uint32_t aBase = sbase + OFF_A + (uint32_t)buf * TILEB;
        const uint32_t bBase = sbase + OFF_B + (uint32_t)buf * TILEB;
        const uint32_t lrow  = (uint32_t)(lane & 15);
        const uint32_t lcol  = (uint32_t)(lane >> 4) * 16u;

        #pragma unroll
        for (int ks = 0; ks < NK32; ks++) {
            uint32_t af[2][4];
            #pragma unroll
            for (int mi = 0; mi < 2; mi++)
                ldm_x4(af[mi], aBase + (uint32_t)(wm * 32 + mi * 16 + lrow) * ASTB
                                     + (uint32_t)ks * 32u + lcol);
            uint32_t bf[8][2];
            #pragma unroll
            for (int njj = 0; njj < 4; njj++) {
                uint32_t r4[4];
                ldm_x4(r4, bBase + (uint32_t)(wn * 64 + njj * 16 + lrow) * ASTB
                                 + (uint32_t)ks * 32u + lcol);
                bf[njj * 2 + 0][0] = r4[0];
                bf[njj * 2 + 1][0] = r4[1];
                bf[njj * 2 + 0][1] = r4[2];
                bf[njj * 2 + 1][1] = r4[3];
            }
            #pragma unroll
            for (int mi = 0; mi < 2; mi++)
                #pragma unroll
                for (int nf = 0; nf < 8; nf++)
                    mma16832_fp8(acc[mi][nf], af[mi], bf[nf]);
        }

        if (b.kb == NKBLK - 1) {
            // ---- chunk epilogue: t = d2*is2; exp(-t)==0 exactly for t>104 ----
            #pragma unroll
            for (int nf = 0; nf < 8; nf++) {
                const int c0 = wn * 64 + nf * 8 + ln;
                const int c1 = c0 + 1;
                const float cc0 = c2S[c0],  cc1 = c2S[c1];
                const float ii0 = is2S[c0], ii1 = is2S[c1];
                #pragma unroll
                for (int mi = 0; mi < 2; mi++) {
                    const float xa = mi ? x2a1 : x2a0;
                    const float xb = mi ? x2b1 : x2b0;
                    const float t00 = fmaxf(xa + cc0 - 2.f * acc[mi][nf][0], 0.f) * ii0;
                    const float t01 = fmaxf(xa + cc1 - 2.f * acc[mi][nf][1], 0.f) * ii1;
                    const float t10 = fmaxf(xb + cc0 - 2.f * acc[mi][nf][2], 0.f) * ii0;
                    const float t11 = fmaxf(xb + cc1 - 2.f * acc[mi][nf][3], 0.f) * ii1;
                    if (t00 < 104.f || t01 < 104.f || t10 < 104.f || t11 < 104.f) {
                        const float p00 = __expf(-t00);
                        const float p01 = __expf(-t01);
                        const float p10 = __expf(-t10);
                        const float p11 = __expf(-t11);
                        #pragma unroll
                        for (int o = 0; o < OUT_DIM; o++) {
                            const float w0 = WcolS[c0 * WST + o];
                            const float w1 = WcolS[c1 * WST + o];
                            oacc[mi * 2 + 0][o] = fmaf(p00, w0, fmaf(p01, w1, oacc[mi * 2 + 0][o]));
                            oacc[mi * 2 + 1][o] = fmaf(p10, w0, fmaf(p11, w1, oacc[mi * 2 + 1][o]));
                        }
                    }
                }
            }
            __syncthreads();   // meta consumed; next chunk may overwrite

            if (b.cl == CHPS - 1) {
                // ---- unit-end: cross-lane + cross-warp reduce, write partial ----
                #pragma unroll
                for (int i = 0; i < 4; i++)
                    #pragma unroll
                    for (int o = 0; o < OUT_DIM; o++) {
                        float v = oacc[i][o];
                        v += __shfl_xor_sync(0xffffffffu, v, 1);
                        v += __shfl_xor_sync(0xffffffffu, v, 2);
                        oacc[i][o] = v;
                    }
                if (wn == 0 && (lane & 3) == 0) {
                    #pragma unroll
                    for (int i = 0; i < 4; i++) {
                        const int r = wm * 32 + (i >> 1) * 16 + (i & 1) * 8 + lm;
                        #pragma unroll
                        for (int o = 0; o < OUT_DIM; o++) redS[r * WST + o] = oacc[i][o];
                    }
                }
                __syncthreads();
                if (wn == 1 && (lane & 3) == 0) {
                    #pragma unroll
                    for (int i = 0; i < 4; i++) {
                        const int r = wm * 32 + (i >> 1) * 16 + (i & 1) * 8 + lm;
                        #pragma unroll
                        for (int o = 0; o < OUT_DIM; o++) redS[r * WST + o] += oacc[i][o];
                    }
                }
                __syncthreads();

                const int slice = b.unit & (NSLICE - 1);
                float* pbase = g_part + (size_t)slice * B_ROWS * OUT_DIM
                             + (size_t)b.m0 * OUT_DIM;
                #pragma unroll
                for (int i = 0; i < 5; i++) {
                    const int e = tid + i * NTHREADS;
                    const int r = e / OUT_DIM;
                    const int o = e - r * OUT_DIM;
                    pbase[(size_t)r * OUT_DIM + o] = redS[r * WST + o];
                }
                #pragma unroll
                for (int i = 0; i < 4; i++)
                    #pragma unroll
                    for (int o = 0; o < OUT_DIM; o++) oacc[i][o] = 0.f;
                __syncthreads();   // redS consumed before next unit reuses it
            }
        }
    }
}

// ---------------------------------------------------------------------------
// Reduce: out = sum of 8 slice partials + bias  (float4 vectorized)
// ---------------------------------------------------------------------------
__global__ void reduce_kernel(const float* __restrict__ bias, float* __restrict__ out) {
    const int t = blockIdx.x * blockDim.x + threadIdx.x;       // float4 index
    const int NQ = (B_ROWS * OUT_DIM) / 4;                     // 40960
    if (t >= NQ) return;
    const int i0 = t * 4;
    float4 s;
    s.x = __ldg(&bias[(i0 + 0) % OUT_DIM]);
    s.y = __ldg(&bias[(i0 + 1) % OUT_DIM]);
    s.z = __ldg(&bias[(i0 + 2) % OUT_DIM]);
    s.w = __ldg(&bias[(i0 + 3) % OUT_DIM]);
    #pragma unroll
    for (int sl = 0; sl < NSLICE; sl++) {
        const float4 p = *(const float4*)&g_part[(size_t)sl * B_ROWS * OUT_DIM + i0];
        s.x += p.x; s.y += p.y; s.z += p.z; s.w += p.w;
    }
    ((float4*)out)[t] = s;
}

// ---------------------------------------------------------------------------
// Launch
// ---------------------------------------------------------------------------
extern "C" void kernel_launch(void* const* d_in, const int* in_sizes, int n_in,
                              void* d_out, int out_size) {
    const float* x       = (const float*)d_in[0];
    const float* centres = (const float*)d_in[1];
    const float* ls      = (const float*)d_in[2];
    const float* W       = (const float*)d_in[3];
    const float* bias    = (const float*)d_in[4];
    float* out           = (float*)d_out;

    int nsm = 148;
    cudaDeviceGetAttribute(&nsm, cudaDevAttrMultiProcessorCount, 0);

    const int nwarps = B_ROWS + C_DIM;              // 18432
    prep_kernel<<<nwarps / 8, 256>>>(x, centres, ls);

    cudaFuncSetAttribute(rbf_mma_kernel,
                         cudaFuncAttributeMaxDynamicSharedMemorySize, SMEM_TOTAL);
    rbf_mma_kernel<<<nsm, NTHREADS, SMEM_TOTAL>>>(W);

    reduce_kernel<<<((B_ROWS * OUT_DIM) / 4 + 255) / 256, 256>>>(bias, out);
}